// round 2
// baseline (speedup 1.0000x reference)
#include <cuda_runtime.h>
#include <math.h>

// Problem constants
#define BDIM   32
#define TENC   1024
#define TDEC   2048
#define DMODEL 256
#define INDIM  80
#define C2     512
#define MTOT   (BDIM*TDEC)   // 65536 total (b,t) rows
#define RSQRT2 0.70710678118654752440f

// ---------------- scratch (device globals; no cudaMalloc allowed) ----------------
__device__ float g_X [(size_t)MTOT*DMODEL];          // 67 MB: shifted linear / conv1 output
__device__ float g_H0[(size_t)MTOT*DMODEL];          // 67 MB: conv0 output
__device__ float g_Q [(size_t)MTOT*DMODEL];          // 67 MB: attention queries
__device__ float g_H1[(size_t)MTOT*DMODEL];          // 67 MB: H0 + context
__device__ float g_S [(size_t)BDIM*TDEC*TENC];       // 268 MB: scores/attn
__device__ float g_Wp0[5*DMODEL*C2];                 // repacked conv weights [tap][ch][n]
__device__ float g_Wp1[5*DMODEL*C2];

__device__ __forceinline__ float sigf(float x) { return 1.0f / (1.0f + __expf(-x)); }

// ---------------- weight repack: (512,256,5) OIH -> [tap*256+ch][512] ----------------
__global__ void __launch_bounds__(256) k_repack(const float* __restrict__ w,
                                                float* __restrict__ wp)
{
    int i = blockIdx.x * 256 + threadIdx.x;
    if (i >= C2 * DMODEL * 5) return;
    int n   = i / (DMODEL * 5);
    int rem = i - n * (DMODEL * 5);
    int ch  = rem / 5;
    int tap = rem - ch * 5;
    wp[(size_t)(tap * DMODEL + ch) * C2 + n] = w[i];
}

// ---------------- K1: x = shift_right(mel @ W_lin^T + b_lin) ----------------
// M=65536, N=256, K=80 (5 BK steps). Row t==0 is exactly zero.
__global__ void __launch_bounds__(256) k_lin_shift(
    const float* __restrict__ mel, const float* __restrict__ W,
    const float* __restrict__ bias, float* __restrict__ out)
{
    __shared__ float As[16][128];
    __shared__ float Bs[16][64];
    const int tid = threadIdx.x;
    const int m0 = blockIdx.x * 128;
    const int n0 = blockIdx.y * 64;
    const int tx = tid & 15, ty = tid >> 4;
    float acc[8][4];
    #pragma unroll
    for (int i = 0; i < 8; ++i)
        #pragma unroll
        for (int j = 0; j < 4; ++j) acc[i][j] = 0.f;

    for (int k0 = 0; k0 < INDIM; k0 += 16) {
        #pragma unroll
        for (int i = 0; i < 2; ++i) {
            int s = tid + i * 256;
            int r = s >> 2, kq = (s & 3) << 2;
            int m = m0 + r;
            int t = m & (TDEC - 1);
            float4 v = make_float4(0.f, 0.f, 0.f, 0.f);
            if (t > 0) v = *(const float4*)(mel + (size_t)(m - 1) * INDIM + k0 + kq);
            As[kq + 0][r] = v.x; As[kq + 1][r] = v.y; As[kq + 2][r] = v.z; As[kq + 3][r] = v.w;
        }
        {
            int n = tid >> 2, kq = (tid & 3) << 2;
            float4 v = *(const float4*)(W + (size_t)(n0 + n) * INDIM + k0 + kq);
            Bs[kq + 0][n] = v.x; Bs[kq + 1][n] = v.y; Bs[kq + 2][n] = v.z; Bs[kq + 3][n] = v.w;
        }
        __syncthreads();
        #pragma unroll
        for (int k = 0; k < 16; ++k) {
            float ar[8], br[4];
            *(float4*)&ar[0] = *(const float4*)&As[k][ty * 8];
            *(float4*)&ar[4] = *(const float4*)&As[k][ty * 8 + 4];
            *(float4*)&br[0] = *(const float4*)&Bs[k][tx * 4];
            #pragma unroll
            for (int i = 0; i < 8; ++i)
                #pragma unroll
                for (int j = 0; j < 4; ++j) acc[i][j] += ar[i] * br[j];
        }
        __syncthreads();
    }
    float4 bb = *(const float4*)(bias + n0 + tx * 4);
    #pragma unroll
    for (int i = 0; i < 8; ++i) {
        int m = m0 + ty * 8 + i;
        int t = m & (TDEC - 1);
        float4 o;
        if (t == 0) { o = make_float4(0.f, 0.f, 0.f, 0.f); }
        else {
            o = make_float4(acc[i][0] + bb.x, acc[i][1] + bb.y,
                            acc[i][2] + bb.z, acc[i][3] + bb.w);
        }
        *(float4*)(out + (size_t)m * DMODEL + n0 + tx * 4) = o;
    }
}

// ---------------- causal conv(k=5, C->2C) + GLU + residual, as 5-tap GEMM ----------------
// in/res: [65536,256], Wp: [5*256][512] k-major, out[m][c] = (a*sig(g)+in)/sqrt2
__global__ void __launch_bounds__(256) k_conv_glu(
    const float* __restrict__ Xin, const float* __restrict__ Wp,
    const float* __restrict__ bias, float* __restrict__ out)
{
    __shared__ float As[16][128];
    __shared__ float Ba[16][64];
    __shared__ float Bg[16][64];
    const int tid = threadIdx.x;
    const int m0 = blockIdx.x * 128;
    const int n0 = blockIdx.y * 64;
    const int tx = tid & 15, ty = tid >> 4;
    float acc_a[8][4], acc_g[8][4];
    #pragma unroll
    for (int i = 0; i < 8; ++i)
        #pragma unroll
        for (int j = 0; j < 4; ++j) { acc_a[i][j] = 0.f; acc_g[i][j] = 0.f; }

    for (int s = 0; s < 80; ++s) {                 // 5 taps x 16 channel-chunks
        const int tap = s >> 4;
        const int ch0 = (s & 15) << 4;
        #pragma unroll
        for (int i = 0; i < 2; ++i) {
            int s2 = tid + i * 256;
            int r = s2 >> 2, kq = (s2 & 3) << 2;
            int m = m0 + r;
            int t = m & (TDEC - 1);
            int ts = t + tap - 4;
            float4 v = make_float4(0.f, 0.f, 0.f, 0.f);
            if (ts >= 0)
                v = *(const float4*)(Xin + (size_t)(m + tap - 4) * DMODEL + ch0 + kq);
            As[kq + 0][r] = v.x; As[kq + 1][r] = v.y; As[kq + 2][r] = v.z; As[kq + 3][r] = v.w;
        }
        {
            int kk = tid >> 4, nq = (tid & 15) << 2;
            const float* wr = Wp + (size_t)((tap << 8) + ch0 + kk) * C2;
            *(float4*)&Ba[kk][nq] = *(const float4*)(wr + n0 + nq);
            *(float4*)&Bg[kk][nq] = *(const float4*)(wr + 256 + n0 + nq);
        }
        __syncthreads();
        #pragma unroll
        for (int k = 0; k < 16; ++k) {
            float ar[8], ba[4], bg[4];
            *(float4*)&ar[0] = *(const float4*)&As[k][ty * 8];
            *(float4*)&ar[4] = *(const float4*)&As[k][ty * 8 + 4];
            *(float4*)&ba[0] = *(const float4*)&Ba[k][tx * 4];
            *(float4*)&bg[0] = *(const float4*)&Bg[k][tx * 4];
            #pragma unroll
            for (int i = 0; i < 8; ++i)
                #pragma unroll
                for (int j = 0; j < 4; ++j) {
                    acc_a[i][j] += ar[i] * ba[j];
                    acc_g[i][j] += ar[i] * bg[j];
                }
        }
        __syncthreads();
    }
    float4 bba = *(const float4*)(bias + n0 + tx * 4);
    float4 bbg = *(const float4*)(bias + 256 + n0 + tx * 4);
    #pragma unroll
    for (int i = 0; i < 8; ++i) {
        int m = m0 + ty * 8 + i;
        float4 res = *(const float4*)(Xin + (size_t)m * DMODEL + n0 + tx * 4);
        float4 o;
        o.x = fmaf(acc_a[i][0] + bba.x, sigf(acc_g[i][0] + bbg.x), res.x) * RSQRT2;
        o.y = fmaf(acc_a[i][1] + bba.y, sigf(acc_g[i][1] + bbg.y), res.y) * RSQRT2;
        o.z = fmaf(acc_a[i][2] + bba.z, sigf(acc_g[i][2] + bbg.z), res.z) * RSQRT2;
        o.w = fmaf(acc_a[i][3] + bba.w, sigf(acc_g[i][3] + bbg.w), res.w) * RSQRT2;
        *(float4*)(out + (size_t)m * DMODEL + n0 + tx * 4) = o;
    }
}

// ---------------- generic NK GEMM: out[m,n] = sum_k A[m,k]*Bw[n,k] (+bias) ----------------
// lda = ldb = K. Optional per-blockIdx.z batch strides. Used for q-GEMM and scores.
__global__ void __launch_bounds__(256) k_gemm_nk(
    const float* __restrict__ A, const float* __restrict__ Bw,
    const float* __restrict__ bias, float* __restrict__ out,
    int K, int ldc, size_t sA, size_t sB, size_t sO)
{
    A  += (size_t)blockIdx.z * sA;
    Bw += (size_t)blockIdx.z * sB;
    out += (size_t)blockIdx.z * sO;
    __shared__ float As[16][128];
    __shared__ float Bs[16][64];
    const int tid = threadIdx.x;
    const int m0 = blockIdx.x * 128;
    const int n0 = blockIdx.y * 64;
    const int tx = tid & 15, ty = tid >> 4;
    float acc[8][4];
    #pragma unroll
    for (int i = 0; i < 8; ++i)
        #pragma unroll
        for (int j = 0; j < 4; ++j) acc[i][j] = 0.f;

    for (int k0 = 0; k0 < K; k0 += 16) {
        #pragma unroll
        for (int i = 0; i < 2; ++i) {
            int s = tid + i * 256;
            int r = s >> 2, kq = (s & 3) << 2;
            float4 v = *(const float4*)(A + (size_t)(m0 + r) * K + k0 + kq);
            As[kq + 0][r] = v.x; As[kq + 1][r] = v.y; As[kq + 2][r] = v.z; As[kq + 3][r] = v.w;
        }
        {
            int n = tid >> 2, kq = (tid & 3) << 2;
            float4 v = *(const float4*)(Bw + (size_t)(n0 + n) * K + k0 + kq);
            Bs[kq + 0][n] = v.x; Bs[kq + 1][n] = v.y; Bs[kq + 2][n] = v.z; Bs[kq + 3][n] = v.w;
        }
        __syncthreads();
        #pragma unroll
        for (int k = 0; k < 16; ++k) {
            float ar[8], br[4];
            *(float4*)&ar[0] = *(const float4*)&As[k][ty * 8];
            *(float4*)&ar[4] = *(const float4*)&As[k][ty * 8 + 4];
            *(float4*)&br[0] = *(const float4*)&Bs[k][tx * 4];
            #pragma unroll
            for (int i = 0; i < 8; ++i)
                #pragma unroll
                for (int j = 0; j < 4; ++j) acc[i][j] += ar[i] * br[j];
        }
        __syncthreads();
    }
    float4 bb = make_float4(0.f, 0.f, 0.f, 0.f);
    if (bias) bb = *(const float4*)(bias + n0 + tx * 4);
    #pragma unroll
    for (int i = 0; i < 8; ++i) {
        int m = m0 + ty * 8 + i;
        float4 o = make_float4(acc[i][0] + bb.x, acc[i][1] + bb.y,
                               acc[i][2] + bb.z, acc[i][3] + bb.w);
        *(float4*)(out + (size_t)m * ldc + n0 + tx * 4) = o;
    }
}

// ---------------- one-pass softmax over rows of S (65536 x 1024) ----------------
__global__ void __launch_bounds__(256) k_softmax(float* __restrict__ S)
{
    const size_t base = (size_t)blockIdx.x * TENC;
    const int tid = threadIdx.x;
    __shared__ float red[8];
    float4 v = *(const float4*)(S + base + tid * 4);
    float mx = fmaxf(fmaxf(v.x, v.y), fmaxf(v.z, v.w));
    #pragma unroll
    for (int o = 16; o > 0; o >>= 1) mx = fmaxf(mx, __shfl_xor_sync(0xffffffffu, mx, o));
    if ((tid & 31) == 0) red[tid >> 5] = mx;
    __syncthreads();
    mx = fmaxf(fmaxf(fmaxf(red[0], red[1]), fmaxf(red[2], red[3])),
               fmaxf(fmaxf(red[4], red[5]), fmaxf(red[6], red[7])));
    __syncthreads();
    v.x = __expf(v.x - mx); v.y = __expf(v.y - mx);
    v.z = __expf(v.z - mx); v.w = __expf(v.w - mx);
    float sm = v.x + v.y + v.z + v.w;
    #pragma unroll
    for (int o = 16; o > 0; o >>= 1) sm += __shfl_xor_sync(0xffffffffu, sm, o);
    if ((tid & 31) == 0) red[tid >> 5] = sm;
    __syncthreads();
    sm = red[0] + red[1] + red[2] + red[3] + red[4] + red[5] + red[6] + red[7];
    float inv = 1.0f / sm;
    v.x *= inv; v.y *= inv; v.z *= inv; v.w *= inv;
    *(float4*)(S + base + tid * 4) = v;
}

// ---------------- context: H1 = H0 + attn @ (enc + first), per batch ----------------
__global__ void __launch_bounds__(256) k_context(
    const float* __restrict__ S, const float* __restrict__ enc,
    const float* __restrict__ first, const float* __restrict__ H0,
    float* __restrict__ H1)
{
    const int b = blockIdx.z;
    const float* A = S + (size_t)b * TDEC * TENC;
    const float* E = enc + (size_t)b * TENC * DMODEL;
    const float* F = first + (size_t)b * TENC * DMODEL;
    __shared__ float As[16][128];
    __shared__ float Bs[16][64];
    const int tid = threadIdx.x;
    const int m0 = blockIdx.x * 128;
    const int n0 = blockIdx.y * 64;
    const int tx = tid & 15, ty = tid >> 4;
    float acc[8][4];
    #pragma unroll
    for (int i = 0; i < 8; ++i)
        #pragma unroll
        for (int j = 0; j < 4; ++j) acc[i][j] = 0.f;

    for (int k0 = 0; k0 < TENC; k0 += 16) {
        #pragma unroll
        for (int i = 0; i < 2; ++i) {
            int s = tid + i * 256;
            int r = s >> 2, kq = (s & 3) << 2;
            float4 v = *(const float4*)(A + (size_t)(m0 + r) * TENC + k0 + kq);
            As[kq + 0][r] = v.x; As[kq + 1][r] = v.y; As[kq + 2][r] = v.z; As[kq + 3][r] = v.w;
        }
        {
            int kk = tid >> 4, nq = (tid & 15) << 2;
            float4 ve = *(const float4*)(E + (size_t)(k0 + kk) * DMODEL + n0 + nq);
            float4 vf = *(const float4*)(F + (size_t)(k0 + kk) * DMODEL + n0 + nq);
            float4 vs = make_float4(ve.x + vf.x, ve.y + vf.y, ve.z + vf.z, ve.w + vf.w);
            *(float4*)&Bs[kk][nq] = vs;
        }
        __syncthreads();
        #pragma unroll
        for (int k = 0; k < 16; ++k) {
            float ar[8], br[4];
            *(float4*)&ar[0] = *(const float4*)&As[k][ty * 8];
            *(float4*)&ar[4] = *(const float4*)&As[k][ty * 8 + 4];
            *(float4*)&br[0] = *(const float4*)&Bs[k][tx * 4];
            #pragma unroll
            for (int i = 0; i < 8; ++i)
                #pragma unroll
                for (int j = 0; j < 4; ++j) acc[i][j] += ar[i] * br[j];
        }
        __syncthreads();
    }
    #pragma unroll
    for (int i = 0; i < 8; ++i) {
        size_t m = (size_t)b * TDEC + m0 + ty * 8 + i;
        float4 h0 = *(const float4*)(H0 + m * DMODEL + n0 + tx * 4);
        float4 o = make_float4(acc[i][0] + h0.x, acc[i][1] + h0.y,
                               acc[i][2] + h0.z, acc[i][3] + h0.w);
        *(float4*)(H1 + m * DMODEL + n0 + tx * 4) = o;
    }
}

// ---------------- final projection: out = H @ W_proj^T + b  (N=80, predicated) ----------------
__global__ void __launch_bounds__(256) k_proj(
    const float* __restrict__ A, const float* __restrict__ W,
    const float* __restrict__ bias, float* __restrict__ out)
{
    __shared__ float As[16][128];
    __shared__ float Bs[16][64];
    const int tid = threadIdx.x;
    const int m0 = blockIdx.x * 128;
    const int n0 = blockIdx.y * 64;
    const int tx = tid & 15, ty = tid >> 4;
    float acc[8][4];
    #pragma unroll
    for (int i = 0; i < 8; ++i)
        #pragma unroll
        for (int j = 0; j < 4; ++j) acc[i][j] = 0.f;

    for (int k0 = 0; k0 < DMODEL; k0 += 16) {
        #pragma unroll
        for (int i = 0; i < 2; ++i) {
            int s = tid + i * 256;
            int r = s >> 2, kq = (s & 3) << 2;
            float4 v = *(const float4*)(A + (size_t)(m0 + r) * DMODEL + k0 + kq);
            As[kq + 0][r] = v.x; As[kq + 1][r] = v.y; As[kq + 2][r] = v.z; As[kq + 3][r] = v.w;
        }
        {
            int n = tid >> 2, kq = (tid & 3) << 2;
            float4 v = make_float4(0.f, 0.f, 0.f, 0.f);
            if (n0 + n < INDIM)
                v = *(const float4*)(W + (size_t)(n0 + n) * DMODEL + k0 + kq);
            Bs[kq + 0][n] = v.x; Bs[kq + 1][n] = v.y; Bs[kq + 2][n] = v.z; Bs[kq + 3][n] = v.w;
        }
        __syncthreads();
        #pragma unroll
        for (int k = 0; k < 16; ++k) {
            float ar[8], br[4];
            *(float4*)&ar[0] = *(const float4*)&As[k][ty * 8];
            *(float4*)&ar[4] = *(const float4*)&As[k][ty * 8 + 4];
            *(float4*)&br[0] = *(const float4*)&Bs[k][tx * 4];
            #pragma unroll
            for (int i = 0; i < 8; ++i)
                #pragma unroll
                for (int j = 0; j < 4; ++j) acc[i][j] += ar[i] * br[j];
        }
        __syncthreads();
    }
    int col = n0 + tx * 4;
    if (col < INDIM) {
        float4 bb = *(const float4*)(bias + col);
        #pragma unroll
        for (int i = 0; i < 8; ++i) {
            int m = m0 + ty * 8 + i;
            float4 o = make_float4(acc[i][0] + bb.x, acc[i][1] + bb.y,
                                   acc[i][2] + bb.z, acc[i][3] + bb.w);
            *(float4*)(out + (size_t)m * INDIM + col) = o;
        }
    }
}

// ---------------- launch ----------------
extern "C" void kernel_launch(void* const* d_in, const int* in_sizes, int n_in,
                              void* d_out, int out_size)
{
    (void)in_sizes; (void)n_in; (void)out_size;
    const float* enc   = (const float*)d_in[0];   // (32,1024,256)
    const float* first = (const float*)d_in[1];   // (32,1024,256)
    const float* mel   = (const float*)d_in[2];   // (32,2048,80)
    const float* W_lin = (const float*)d_in[3];   // (256,80)
    const float* b_lin = (const float*)d_in[4];   // (256)
    const float* cw0   = (const float*)d_in[5];   // (512,256,5)
    const float* cb0   = (const float*)d_in[6];   // (512)
    const float* cw1   = (const float*)d_in[7];   // (512,256,5)
    const float* cb1   = (const float*)d_in[8];   // (512)
    const float* W_att = (const float*)d_in[9];   // (256,256)
    const float* b_att = (const float*)d_in[10];  // (256)
    const float* W_prj = (const float*)d_in[11];  // (80,256)
    const float* b_prj = (const float*)d_in[12];  // (80)
    float* out = (float*)d_out;                   // (32,2048,80) f32

    float *X, *H0, *Q, *H1, *S, *Wp0, *Wp1;
    cudaGetSymbolAddress((void**)&X,  g_X);
    cudaGetSymbolAddress((void**)&H0, g_H0);
    cudaGetSymbolAddress((void**)&Q,  g_Q);
    cudaGetSymbolAddress((void**)&H1, g_H1);
    cudaGetSymbolAddress((void**)&S,  g_S);
    cudaGetSymbolAddress((void**)&Wp0, g_Wp0);
    cudaGetSymbolAddress((void**)&Wp1, g_Wp1);

    // 1) repack conv weights to k-major
    k_repack<<<(C2 * DMODEL * 5 + 255) / 256, 256>>>(cw0, Wp0);
    k_repack<<<(C2 * DMODEL * 5 + 255) / 256, 256>>>(cw1, Wp1);
    // 2) shifted input linear
    k_lin_shift<<<dim3(MTOT / 128, DMODEL / 64), 256>>>(mel, W_lin, b_lin, X);
    // 3) conv-GLU layer 0
    k_conv_glu<<<dim3(MTOT / 128, DMODEL / 64), 256>>>(X, Wp0, cb0, H0);
    // 4) queries
    k_gemm_nk<<<dim3(MTOT / 128, DMODEL / 64, 1), 256>>>(
        H0, W_att, b_att, Q, DMODEL, DMODEL, 0, 0, 0);
    // 5) attention scores (per batch)
    k_gemm_nk<<<dim3(TDEC / 128, TENC / 64, BDIM), 256>>>(
        Q, enc, nullptr, S, DMODEL, TENC,
        (size_t)TDEC * DMODEL, (size_t)TENC * DMODEL, (size_t)TDEC * TENC);
    // 6) softmax
    k_softmax<<<MTOT, 256>>>(S);
    // 7) context + residual: H1 = H0 + attn @ (enc+first)
    k_context<<<dim3(TDEC / 128, DMODEL / 64, BDIM), 256>>>(S, enc, first, H0, H1);
    // 8) conv-GLU layer 1 (output into X, which is free now)
    k_conv_glu<<<dim3(MTOT / 128, DMODEL / 64), 256>>>(H1, Wp1, cb1, X);
    // 9) output projection
    k_proj<<<dim3(MTOT / 128, 2), 256>>>(X, W_prj, b_prj, out);
}

// round 3
// speedup vs baseline: 1.0878x; 1.0878x over previous
#include <cuda_runtime.h>
#include <math.h>

// Problem constants
#define BDIM   32
#define TENC   1024
#define TDEC   2048
#define DMODEL 256
#define INDIM  80
#define C2     512
#define MTOT   (BDIM*TDEC)   // 65536 total (b,t) rows
#define RSQRT2 0.70710678118654752440f

typedef unsigned long long u64;

// ---------------- scratch (device globals; no cudaMalloc allowed) ----------------
__device__ float g_X [(size_t)MTOT*DMODEL];          // 67 MB
__device__ float g_H0[(size_t)MTOT*DMODEL];          // 67 MB
__device__ float g_Q [(size_t)MTOT*DMODEL];          // 67 MB
__device__ float g_H1[(size_t)MTOT*DMODEL];          // 67 MB
__device__ float g_S [(size_t)BDIM*TDEC*TENC];       // 268 MB
__device__ float g_Wp0[5*DMODEL*C2];
__device__ float g_Wp1[5*DMODEL*C2];

__device__ __forceinline__ float sigf(float x) { return 1.0f / (1.0f + __expf(-x)); }

// ------- packed f32x2 helpers (FFMA2: 2 fp32 FMAs per fma-pipe instruction) -------
__device__ __forceinline__ u64 pack_dup(float x) {
    u64 r; asm("mov.b64 %0, {%1, %1};" : "=l"(r) : "f"(x)); return r;
}
__device__ __forceinline__ void ffma2(u64 &d, u64 a, u64 b) {
    asm("fma.rn.f32x2 %0, %1, %2, %0;" : "+l"(d) : "l"(a), "l"(b));
}
__device__ __forceinline__ float2 unpk(u64 v) {
    float lo, hi; asm("mov.b64 {%0, %1}, %2;" : "=f"(lo), "=f"(hi) : "l"(v));
    return make_float2(lo, hi);
}

// ---------------- weight repack: (512,256,5) OIH -> [tap*256+ch][512] ----------------
__global__ void __launch_bounds__(256) k_repack(const float* __restrict__ w,
                                                float* __restrict__ wp)
{
    int i = blockIdx.x * 256 + threadIdx.x;
    if (i >= C2 * DMODEL * 5) return;
    int n   = i / (DMODEL * 5);
    int rem = i - n * (DMODEL * 5);
    int ch  = rem / 5;
    int tap = rem - ch * 5;
    wp[(size_t)(tap * DMODEL + ch) * C2 + n] = w[i];
}

// ---------------- K1: x = shift_right(mel @ W_lin^T + b_lin) ----------------
__global__ void __launch_bounds__(256) k_lin_shift(
    const float* __restrict__ mel, const float* __restrict__ W,
    const float* __restrict__ bias, float* __restrict__ out)
{
    __shared__ float As[16][128];
    __shared__ float Bs[16][64];
    const int tid = threadIdx.x;
    const int m0 = blockIdx.x * 128;
    const int n0 = blockIdx.y * 64;
    const int tx = tid & 15, ty = tid >> 4;
    u64 acc[4][4];
    #pragma unroll
    for (int i = 0; i < 4; ++i)
        #pragma unroll
        for (int j = 0; j < 4; ++j) acc[i][j] = 0ULL;

    for (int k0 = 0; k0 < INDIM; k0 += 16) {
        #pragma unroll
        for (int i = 0; i < 2; ++i) {
            int s = tid + i * 256;
            int r = s >> 2, kq = (s & 3) << 2;
            int m = m0 + r;
            int t = m & (TDEC - 1);
            float4 v = make_float4(0.f, 0.f, 0.f, 0.f);
            if (t > 0) v = *(const float4*)(mel + (size_t)(m - 1) * INDIM + k0 + kq);
            As[kq + 0][r] = v.x; As[kq + 1][r] = v.y; As[kq + 2][r] = v.z; As[kq + 3][r] = v.w;
        }
        {
            int n = tid >> 2, kq = (tid & 3) << 2;
            float4 v = *(const float4*)(W + (size_t)(n0 + n) * INDIM + k0 + kq);
            Bs[kq + 0][n] = v.x; Bs[kq + 1][n] = v.y; Bs[kq + 2][n] = v.z; Bs[kq + 3][n] = v.w;
        }
        __syncthreads();
        #pragma unroll
        for (int k = 0; k < 16; ++k) {
            ulonglong2 aa0 = *(const ulonglong2*)&As[k][ty * 8];
            ulonglong2 aa1 = *(const ulonglong2*)&As[k][ty * 8 + 4];
            float4 br = *(const float4*)&Bs[k][tx * 4];
            u64 b0 = pack_dup(br.x), b1 = pack_dup(br.y), b2 = pack_dup(br.z), b3 = pack_dup(br.w);
            ffma2(acc[0][0], aa0.x, b0); ffma2(acc[0][1], aa0.x, b1);
            ffma2(acc[0][2], aa0.x, b2); ffma2(acc[0][3], aa0.x, b3);
            ffma2(acc[1][0], aa0.y, b0); ffma2(acc[1][1], aa0.y, b1);
            ffma2(acc[1][2], aa0.y, b2); ffma2(acc[1][3], aa0.y, b3);
            ffma2(acc[2][0], aa1.x, b0); ffma2(acc[2][1], aa1.x, b1);
            ffma2(acc[2][2], aa1.x, b2); ffma2(acc[2][3], aa1.x, b3);
            ffma2(acc[3][0], aa1.y, b0); ffma2(acc[3][1], aa1.y, b1);
            ffma2(acc[3][2], aa1.y, b2); ffma2(acc[3][3], aa1.y, b3);
        }
        __syncthreads();
    }
    float4 bb = *(const float4*)(bias + n0 + tx * 4);
    #pragma unroll
    for (int i2 = 0; i2 < 4; ++i2) {
        float2 c0 = unpk(acc[i2][0]), c1 = unpk(acc[i2][1]);
        float2 c2 = unpk(acc[i2][2]), c3 = unpk(acc[i2][3]);
        int m = m0 + ty * 8 + 2 * i2;
        #pragma unroll
        for (int h = 0; h < 2; ++h) {
            int mm = m + h;
            int t = mm & (TDEC - 1);
            float4 o;
            if (t == 0) o = make_float4(0.f, 0.f, 0.f, 0.f);
            else if (h == 0)
                o = make_float4(c0.x + bb.x, c1.x + bb.y, c2.x + bb.z, c3.x + bb.w);
            else
                o = make_float4(c0.y + bb.x, c1.y + bb.y, c2.y + bb.z, c3.y + bb.w);
            *(float4*)(out + (size_t)mm * DMODEL + n0 + tx * 4) = o;
        }
    }
}

// ---------------- causal conv(k=5, C->2C) + GLU + residual, as 5-tap GEMM ----------------
__global__ void __launch_bounds__(256) k_conv_glu(
    const float* __restrict__ Xin, const float* __restrict__ Wp,
    const float* __restrict__ bias, float* __restrict__ out)
{
    __shared__ float As[16][128];
    __shared__ float Ba[16][64];
    __shared__ float Bg[16][64];
    const int tid = threadIdx.x;
    const int m0 = blockIdx.x * 128;
    const int n0 = blockIdx.y * 64;
    const int tx = tid & 15, ty = tid >> 4;
    u64 aAcc[4][4], gAcc[4][4];
    #pragma unroll
    for (int i = 0; i < 4; ++i)
        #pragma unroll
        for (int j = 0; j < 4; ++j) { aAcc[i][j] = 0ULL; gAcc[i][j] = 0ULL; }

    for (int s = 0; s < 80; ++s) {                 // 5 taps x 16 channel-chunks
        const int tap = s >> 4;
        const int ch0 = (s & 15) << 4;
        #pragma unroll
        for (int i = 0; i < 2; ++i) {
            int s2 = tid + i * 256;
            int r = s2 >> 2, kq = (s2 & 3) << 2;
            int m = m0 + r;
            int t = m & (TDEC - 1);
            int ts = t + tap - 4;
            float4 v = make_float4(0.f, 0.f, 0.f, 0.f);
            if (ts >= 0)
                v = *(const float4*)(Xin + (size_t)(m + tap - 4) * DMODEL + ch0 + kq);
            As[kq + 0][r] = v.x; As[kq + 1][r] = v.y; As[kq + 2][r] = v.z; As[kq + 3][r] = v.w;
        }
        {
            int kk = tid >> 4, nq = (tid & 15) << 2;
            const float* wr = Wp + (size_t)((tap << 8) + ch0 + kk) * C2;
            *(float4*)&Ba[kk][nq] = *(const float4*)(wr + n0 + nq);
            *(float4*)&Bg[kk][nq] = *(const float4*)(wr + 256 + n0 + nq);
        }
        __syncthreads();
        #pragma unroll
        for (int k = 0; k < 16; ++k) {
            ulonglong2 aa0 = *(const ulonglong2*)&As[k][ty * 8];
            ulonglong2 aa1 = *(const ulonglong2*)&As[k][ty * 8 + 4];
            float4 ba = *(const float4*)&Ba[k][tx * 4];
            float4 bg = *(const float4*)&Bg[k][tx * 4];
            u64 a0 = pack_dup(ba.x), a1 = pack_dup(ba.y), a2 = pack_dup(ba.z), a3 = pack_dup(ba.w);
            u64 g0 = pack_dup(bg.x), g1 = pack_dup(bg.y), g2 = pack_dup(bg.z), g3 = pack_dup(bg.w);
            ffma2(aAcc[0][0], aa0.x, a0); ffma2(aAcc[0][1], aa0.x, a1);
            ffma2(aAcc[0][2], aa0.x, a2); ffma2(aAcc[0][3], aa0.x, a3);
            ffma2(gAcc[0][0], aa0.x, g0); ffma2(gAcc[0][1], aa0.x, g1);
            ffma2(gAcc[0][2], aa0.x, g2); ffma2(gAcc[0][3], aa0.x, g3);
            ffma2(aAcc[1][0], aa0.y, a0); ffma2(aAcc[1][1], aa0.y, a1);
            ffma2(aAcc[1][2], aa0.y, a2); ffma2(aAcc[1][3], aa0.y, a3);
            ffma2(gAcc[1][0], aa0.y, g0); ffma2(gAcc[1][1], aa0.y, g1);
            ffma2(gAcc[1][2], aa0.y, g2); ffma2(gAcc[1][3], aa0.y, g3);
            ffma2(aAcc[2][0], aa1.x, a0); ffma2(aAcc[2][1], aa1.x, a1);
            ffma2(aAcc[2][2], aa1.x, a2); ffma2(aAcc[2][3], aa1.x, a3);
            ffma2(gAcc[2][0], aa1.x, g0); ffma2(gAcc[2][1], aa1.x, g1);
            ffma2(gAcc[2][2], aa1.x, g2); ffma2(gAcc[2][3], aa1.x, g3);
            ffma2(aAcc[3][0], aa1.y, a0); ffma2(aAcc[3][1], aa1.y, a1);
            ffma2(aAcc[3][2], aa1.y, a2); ffma2(aAcc[3][3], aa1.y, a3);
            ffma2(gAcc[3][0], aa1.y, g0); ffma2(gAcc[3][1], aa1.y, g1);
            ffma2(gAcc[3][2], aa1.y, g2); ffma2(gAcc[3][3], aa1.y, g3);
        }
        __syncthreads();
    }
    float4 bba = *(const float4*)(bias + n0 + tx * 4);
    float4 bbg = *(const float4*)(bias + 256 + n0 + tx * 4);
    #pragma unroll
    for (int i2 = 0; i2 < 4; ++i2) {
        float2 a0 = unpk(aAcc[i2][0]), a1 = unpk(aAcc[i2][1]);
        float2 a2 = unpk(aAcc[i2][2]), a3 = unpk(aAcc[i2][3]);
        float2 g0 = unpk(gAcc[i2][0]), g1 = unpk(gAcc[i2][1]);
        float2 g2 = unpk(gAcc[i2][2]), g3 = unpk(gAcc[i2][3]);
        int m = m0 + ty * 8 + 2 * i2;
        {
            float4 res = *(const float4*)(Xin + (size_t)m * DMODEL + n0 + tx * 4);
            float4 o;
            o.x = fmaf(a0.x + bba.x, sigf(g0.x + bbg.x), res.x) * RSQRT2;
            o.y = fmaf(a1.x + bba.y, sigf(g1.x + bbg.y), res.y) * RSQRT2;
            o.z = fmaf(a2.x + bba.z, sigf(g2.x + bbg.z), res.z) * RSQRT2;
            o.w = fmaf(a3.x + bba.w, sigf(g3.x + bbg.w), res.w) * RSQRT2;
            *(float4*)(out + (size_t)m * DMODEL + n0 + tx * 4) = o;
        }
        {
            float4 res = *(const float4*)(Xin + (size_t)(m + 1) * DMODEL + n0 + tx * 4);
            float4 o;
            o.x = fmaf(a0.y + bba.x, sigf(g0.y + bbg.x), res.x) * RSQRT2;
            o.y = fmaf(a1.y + bba.y, sigf(g1.y + bbg.y), res.y) * RSQRT2;
            o.z = fmaf(a2.y + bba.z, sigf(g2.y + bbg.z), res.z) * RSQRT2;
            o.w = fmaf(a3.y + bba.w, sigf(g3.y + bbg.w), res.w) * RSQRT2;
            *(float4*)(out + (size_t)(m + 1) * DMODEL + n0 + tx * 4) = o;
        }
    }
}

// ---------------- generic NK GEMM: out[m,n] = sum_k A[m,k]*Bw[n,k] (+bias) ----------------
__global__ void __launch_bounds__(256) k_gemm_nk(
    const float* __restrict__ A, const float* __restrict__ Bw,
    const float* __restrict__ bias, float* __restrict__ out,
    int K, int ldc, size_t sA, size_t sB, size_t sO)
{
    A  += (size_t)blockIdx.z * sA;
    Bw += (size_t)blockIdx.z * sB;
    out += (size_t)blockIdx.z * sO;
    __shared__ float As[16][128];
    __shared__ float Bs[16][64];
    const int tid = threadIdx.x;
    const int m0 = blockIdx.x * 128;
    const int n0 = blockIdx.y * 64;
    const int tx = tid & 15, ty = tid >> 4;
    u64 acc[4][4];
    #pragma unroll
    for (int i = 0; i < 4; ++i)
        #pragma unroll
        for (int j = 0; j < 4; ++j) acc[i][j] = 0ULL;

    for (int k0 = 0; k0 < K; k0 += 16) {
        #pragma unroll
        for (int i = 0; i < 2; ++i) {
            int s = tid + i * 256;
            int r = s >> 2, kq = (s & 3) << 2;
            float4 v = *(const float4*)(A + (size_t)(m0 + r) * K + k0 + kq);
            As[kq + 0][r] = v.x; As[kq + 1][r] = v.y; As[kq + 2][r] = v.z; As[kq + 3][r] = v.w;
        }
        {
            int n = tid >> 2, kq = (tid & 3) << 2;
            float4 v = *(const float4*)(Bw + (size_t)(n0 + n) * K + k0 + kq);
            Bs[kq + 0][n] = v.x; Bs[kq + 1][n] = v.y; Bs[kq + 2][n] = v.z; Bs[kq + 3][n] = v.w;
        }
        __syncthreads();
        #pragma unroll
        for (int k = 0; k < 16; ++k) {
            ulonglong2 aa0 = *(const ulonglong2*)&As[k][ty * 8];
            ulonglong2 aa1 = *(const ulonglong2*)&As[k][ty * 8 + 4];
            float4 br = *(const float4*)&Bs[k][tx * 4];
            u64 b0 = pack_dup(br.x), b1 = pack_dup(br.y), b2 = pack_dup(br.z), b3 = pack_dup(br.w);
            ffma2(acc[0][0], aa0.x, b0); ffma2(acc[0][1], aa0.x, b1);
            ffma2(acc[0][2], aa0.x, b2); ffma2(acc[0][3], aa0.x, b3);
            ffma2(acc[1][0], aa0.y, b0); ffma2(acc[1][1], aa0.y, b1);
            ffma2(acc[1][2], aa0.y, b2); ffma2(acc[1][3], aa0.y, b3);
            ffma2(acc[2][0], aa1.x, b0); ffma2(acc[2][1], aa1.x, b1);
            ffma2(acc[2][2], aa1.x, b2); ffma2(acc[2][3], aa1.x, b3);
            ffma2(acc[3][0], aa1.y, b0); ffma2(acc[3][1], aa1.y, b1);
            ffma2(acc[3][2], aa1.y, b2); ffma2(acc[3][3], aa1.y, b3);
        }
        __syncthreads();
    }
    float4 bb = make_float4(0.f, 0.f, 0.f, 0.f);
    if (bias) bb = *(const float4*)(bias + n0 + tx * 4);
    #pragma unroll
    for (int i2 = 0; i2 < 4; ++i2) {
        float2 c0 = unpk(acc[i2][0]), c1 = unpk(acc[i2][1]);
        float2 c2 = unpk(acc[i2][2]), c3 = unpk(acc[i2][3]);
        int m = m0 + ty * 8 + 2 * i2;
        *(float4*)(out + (size_t)m * ldc + n0 + tx * 4) =
            make_float4(c0.x + bb.x, c1.x + bb.y, c2.x + bb.z, c3.x + bb.w);
        *(float4*)(out + (size_t)(m + 1) * ldc + n0 + tx * 4) =
            make_float4(c0.y + bb.x, c1.y + bb.y, c2.y + bb.z, c3.y + bb.w);
    }
}

// ---------------- one-pass softmax over rows of S (65536 x 1024) ----------------
__global__ void __launch_bounds__(256) k_softmax(float* __restrict__ S)
{
    const size_t base = (size_t)blockIdx.x * TENC;
    const int tid = threadIdx.x;
    __shared__ float red[8];
    float4 v = *(const float4*)(S + base + tid * 4);
    float mx = fmaxf(fmaxf(v.x, v.y), fmaxf(v.z, v.w));
    #pragma unroll
    for (int o = 16; o > 0; o >>= 1) mx = fmaxf(mx, __shfl_xor_sync(0xffffffffu, mx, o));
    if ((tid & 31) == 0) red[tid >> 5] = mx;
    __syncthreads();
    mx = fmaxf(fmaxf(fmaxf(red[0], red[1]), fmaxf(red[2], red[3])),
               fmaxf(fmaxf(red[4], red[5]), fmaxf(red[6], red[7])));
    __syncthreads();
    v.x = __expf(v.x - mx); v.y = __expf(v.y - mx);
    v.z = __expf(v.z - mx); v.w = __expf(v.w - mx);
    float sm = v.x + v.y + v.z + v.w;
    #pragma unroll
    for (int o = 16; o > 0; o >>= 1) sm += __shfl_xor_sync(0xffffffffu, sm, o);
    if ((tid & 31) == 0) red[tid >> 5] = sm;
    __syncthreads();
    sm = red[0] + red[1] + red[2] + red[3] + red[4] + red[5] + red[6] + red[7];
    float inv = 1.0f / sm;
    v.x *= inv; v.y *= inv; v.z *= inv; v.w *= inv;
    *(float4*)(S + base + tid * 4) = v;
}

// ---------------- context: H1 = H0 + attn @ (enc + first), per batch ----------------
__global__ void __launch_bounds__(256) k_context(
    const float* __restrict__ S, const float* __restrict__ enc,
    const float* __restrict__ first, const float* __restrict__ H0,
    float* __restrict__ H1)
{
    const int b = blockIdx.z;
    const float* A = S + (size_t)b * TDEC * TENC;
    const float* E = enc + (size_t)b * TENC * DMODEL;
    const float* F = first + (size_t)b * TENC * DMODEL;
    __shared__ float As[16][128];
    __shared__ float Bs[16][64];
    const int tid = threadIdx.x;
    const int m0 = blockIdx.x * 128;
    const int n0 = blockIdx.y * 64;
    const int tx = tid & 15, ty = tid >> 4;
    u64 acc[4][4];
    #pragma unroll
    for (int i = 0; i < 4; ++i)
        #pragma unroll
        for (int j = 0; j < 4; ++j) acc[i][j] = 0ULL;

    for (int k0 = 0; k0 < TENC; k0 += 16) {
        #pragma unroll
        for (int i = 0; i < 2; ++i) {
            int s = tid + i * 256;
            int r = s >> 2, kq = (s & 3) << 2;
            float4 v = *(const float4*)(A + (size_t)(m0 + r) * TENC + k0 + kq);
            As[kq + 0][r] = v.x; As[kq + 1][r] = v.y; As[kq + 2][r] = v.z; As[kq + 3][r] = v.w;
        }
        {
            int kk = tid >> 4, nq = (tid & 15) << 2;
            float4 ve = *(const float4*)(E + (size_t)(k0 + kk) * DMODEL + n0 + nq);
            float4 vf = *(const float4*)(F + (size_t)(k0 + kk) * DMODEL + n0 + nq);
            *(float4*)&Bs[kk][nq] = make_float4(ve.x + vf.x, ve.y + vf.y,
                                                ve.z + vf.z, ve.w + vf.w);
        }
        __syncthreads();
        #pragma unroll
        for (int k = 0; k < 16; ++k) {
            ulonglong2 aa0 = *(const ulonglong2*)&As[k][ty * 8];
            ulonglong2 aa1 = *(const ulonglong2*)&As[k][ty * 8 + 4];
            float4 br = *(const float4*)&Bs[k][tx * 4];
            u64 b0 = pack_dup(br.x), b1 = pack_dup(br.y), b2 = pack_dup(br.z), b3 = pack_dup(br.w);
            ffma2(acc[0][0], aa0.x, b0); ffma2(acc[0][1], aa0.x, b1);
            ffma2(acc[0][2], aa0.x, b2); ffma2(acc[0][3], aa0.x, b3);
            ffma2(acc[1][0], aa0.y, b0); ffma2(acc[1][1], aa0.y, b1);
            ffma2(acc[1][2], aa0.y, b2); ffma2(acc[1][3], aa0.y, b3);
            ffma2(acc[2][0], aa1.x, b0); ffma2(acc[2][1], aa1.x, b1);
            ffma2(acc[2][2], aa1.x, b2); ffma2(acc[2][3], aa1.x, b3);
            ffma2(acc[3][0], aa1.y, b0); ffma2(acc[3][1], aa1.y, b1);
            ffma2(acc[3][2], aa1.y, b2); ffma2(acc[3][3], aa1.y, b3);
        }
        __syncthreads();
    }
    #pragma unroll
    for (int i2 = 0; i2 < 4; ++i2) {
        float2 c0 = unpk(acc[i2][0]), c1 = unpk(acc[i2][1]);
        float2 c2 = unpk(acc[i2][2]), c3 = unpk(acc[i2][3]);
        size_t m = (size_t)b * TDEC + m0 + ty * 8 + 2 * i2;
        float4 h0 = *(const float4*)(H0 + m * DMODEL + n0 + tx * 4);
        *(float4*)(H1 + m * DMODEL + n0 + tx * 4) =
            make_float4(c0.x + h0.x, c1.x + h0.y, c2.x + h0.z, c3.x + h0.w);
        float4 h1 = *(const float4*)(H0 + (m + 1) * DMODEL + n0 + tx * 4);
        *(float4*)(H1 + (m + 1) * DMODEL + n0 + tx * 4) =
            make_float4(c0.y + h1.x, c1.y + h1.y, c2.y + h1.z, c3.y + h1.w);
    }
}

// ---------------- final projection: out = H @ W_proj^T + b  (N=80, predicated) ----------------
__global__ void __launch_bounds__(256) k_proj(
    const float* __restrict__ A, const float* __restrict__ W,
    const float* __restrict__ bias, float* __restrict__ out)
{
    __shared__ float As[16][128];
    __shared__ float Bs[16][64];
    const int tid = threadIdx.x;
    const int m0 = blockIdx.x * 128;
    const int n0 = blockIdx.y * 64;
    const int tx = tid & 15, ty = tid >> 4;
    u64 acc[4][4];
    #pragma unroll
    for (int i = 0; i < 4; ++i)
        #pragma unroll
        for (int j = 0; j < 4; ++j) acc[i][j] = 0ULL;

    for (int k0 = 0; k0 < DMODEL; k0 += 16) {
        #pragma unroll
        for (int i = 0; i < 2; ++i) {
            int s = tid + i * 256;
            int r = s >> 2, kq = (s & 3) << 2;
            float4 v = *(const float4*)(A + (size_t)(m0 + r) * DMODEL + k0 + kq);
            As[kq + 0][r] = v.x; As[kq + 1][r] = v.y; As[kq + 2][r] = v.z; As[kq + 3][r] = v.w;
        }
        {
            int n = tid >> 2, kq = (tid & 3) << 2;
            float4 v = make_float4(0.f, 0.f, 0.f, 0.f);
            if (n0 + n < INDIM)
                v = *(const float4*)(W + (size_t)(n0 + n) * DMODEL + k0 + kq);
            Bs[kq + 0][n] = v.x; Bs[kq + 1][n] = v.y; Bs[kq + 2][n] = v.z; Bs[kq + 3][n] = v.w;
        }
        __syncthreads();
        #pragma unroll
        for (int k = 0; k < 16; ++k) {
            ulonglong2 aa0 = *(const ulonglong2*)&As[k][ty * 8];
            ulonglong2 aa1 = *(const ulonglong2*)&As[k][ty * 8 + 4];
            float4 br = *(const float4*)&Bs[k][tx * 4];
            u64 b0 = pack_dup(br.x), b1 = pack_dup(br.y), b2 = pack_dup(br.z), b3 = pack_dup(br.w);
            ffma2(acc[0][0], aa0.x, b0); ffma2(acc[0][1], aa0.x, b1);
            ffma2(acc[0][2], aa0.x, b2); ffma2(acc[0][3], aa0.x, b3);
            ffma2(acc[1][0], aa0.y, b0); ffma2(acc[1][1], aa0.y, b1);
            ffma2(acc[1][2], aa0.y, b2); ffma2(acc[1][3], aa0.y, b3);
            ffma2(acc[2][0], aa1.x, b0); ffma2(acc[2][1], aa1.x, b1);
            ffma2(acc[2][2], aa1.x, b2); ffma2(acc[2][3], aa1.x, b3);
            ffma2(acc[3][0], aa1.y, b0); ffma2(acc[3][1], aa1.y, b1);
            ffma2(acc[3][2], aa1.y, b2); ffma2(acc[3][3], aa1.y, b3);
        }
        __syncthreads();
    }
    int col = n0 + tx * 4;
    if (col < INDIM) {
        float4 bb = *(const float4*)(bias + col);
        #pragma unroll
        for (int i2 = 0; i2 < 4; ++i2) {
            float2 c0 = unpk(acc[i2][0]), c1 = unpk(acc[i2][1]);
            float2 c2 = unpk(acc[i2][2]), c3 = unpk(acc[i2][3]);
            int m = m0 + ty * 8 + 2 * i2;
            *(float4*)(out + (size_t)m * INDIM + col) =
                make_float4(c0.x + bb.x, c1.x + bb.y, c2.x + bb.z, c3.x + bb.w);
            *(float4*)(out + (size_t)(m + 1) * INDIM + col) =
                make_float4(c0.y + bb.x, c1.y + bb.y, c2.y + bb.z, c3.y + bb.w);
        }
    }
}

// ---------------- launch ----------------
extern "C" void kernel_launch(void* const* d_in, const int* in_sizes, int n_in,
                              void* d_out, int out_size)
{
    (void)in_sizes; (void)n_in; (void)out_size;
    const float* enc   = (const float*)d_in[0];
    const float* first = (const float*)d_in[1];
    const float* mel   = (const float*)d_in[2];
    const float* W_lin = (const float*)d_in[3];
    const float* b_lin = (const float*)d_in[4];
    const float* cw0   = (const float*)d_in[5];
    const float* cb0   = (const float*)d_in[6];
    const float* cw1   = (const float*)d_in[7];
    const float* cb1   = (const float*)d_in[8];
    const float* W_att = (const float*)d_in[9];
    const float* b_att = (const float*)d_in[10];
    const float* W_prj = (const float*)d_in[11];
    const float* b_prj = (const float*)d_in[12];
    float* out = (float*)d_out;

    float *X, *H0, *Q, *H1, *S, *Wp0, *Wp1;
    cudaGetSymbolAddress((void**)&X,  g_X);
    cudaGetSymbolAddress((void**)&H0, g_H0);
    cudaGetSymbolAddress((void**)&Q,  g_Q);
    cudaGetSymbolAddress((void**)&H1, g_H1);
    cudaGetSymbolAddress((void**)&S,  g_S);
    cudaGetSymbolAddress((void**)&Wp0, g_Wp0);
    cudaGetSymbolAddress((void**)&Wp1, g_Wp1);

    k_repack<<<(C2 * DMODEL * 5 + 255) / 256, 256>>>(cw0, Wp0);
    k_repack<<<(C2 * DMODEL * 5 + 255) / 256, 256>>>(cw1, Wp1);
    k_lin_shift<<<dim3(MTOT / 128, DMODEL / 64), 256>>>(mel, W_lin, b_lin, X);
    k_conv_glu<<<dim3(MTOT / 128, DMODEL / 64), 256>>>(X, Wp0, cb0, H0);
    k_gemm_nk<<<dim3(MTOT / 128, DMODEL / 64, 1), 256>>>(
        H0, W_att, b_att, Q, DMODEL, DMODEL, 0, 0, 0);
    k_gemm_nk<<<dim3(TDEC / 128, TENC / 64, BDIM), 256>>>(
        Q, enc, nullptr, S, DMODEL, TENC,
        (size_t)TDEC * DMODEL, (size_t)TENC * DMODEL, (size_t)TDEC * TENC);
    k_softmax<<<MTOT, 256>>>(S);
    k_context<<<dim3(TDEC / 128, DMODEL / 64, BDIM), 256>>>(S, enc, first, H0, H1);
    k_conv_glu<<<dim3(MTOT / 128, DMODEL / 64), 256>>>(H1, Wp1, cb1, X);
    k_proj<<<dim3(MTOT / 128, 2), 256>>>(X, W_prj, b_prj, out);
}

// round 5
// speedup vs baseline: 1.1504x; 1.0575x over previous
#include <cuda_runtime.h>
#include <math.h>
#include <stdint.h>
#include <mma.h>

using namespace nvcuda;

// Problem constants
#define BDIM   32
#define TENC   1024
#define TDEC   2048
#define DMODEL 256
#define INDIM  80
#define C2     512
#define MTOT   (BDIM*TDEC)   // 65536 total (b,t) rows
#define RSQRT2 0.70710678118654752440f

typedef unsigned long long u64;

// ---------------- scratch (device globals; no cudaMalloc allowed) ----------------
__device__ float g_X [(size_t)MTOT*DMODEL];
__device__ float g_H0[(size_t)MTOT*DMODEL];
__device__ float g_Q [(size_t)MTOT*DMODEL];
__device__ float g_H1[(size_t)MTOT*DMODEL];
__device__ float g_S [(size_t)BDIM*TDEC*TENC];
__device__ float g_Wb0[(size_t)C2*1280];   // repacked conv weights [n][tap*256+ch]
__device__ float g_Wb1[(size_t)C2*1280];

__device__ __forceinline__ float sigf(float x) { return 1.0f / (1.0f + __expf(-x)); }

// ------- packed f32x2 helpers -------
__device__ __forceinline__ u64 pack_dup(float x) {
    u64 r; asm("mov.b64 %0, {%1, %1};" : "=l"(r) : "f"(x)); return r;
}
__device__ __forceinline__ void ffma2(u64 &d, u64 a, u64 b) {
    asm("fma.rn.f32x2 %0, %1, %2, %0;" : "+l"(d) : "l"(a), "l"(b));
}
__device__ __forceinline__ float2 unpk(u64 v) {
    float lo, hi; asm("mov.b64 {%0, %1}, %2;" : "=f"(lo), "=f"(hi) : "l"(v));
    return make_float2(lo, hi);
}

// ---------------- conv weight repack: w[n][ch][tap] -> Wb[n][tap*256+ch] ----------------
__global__ void __launch_bounds__(256) k_repack_nk(const float* __restrict__ w,
                                                   float* __restrict__ wb)
{
    int i = blockIdx.x * 256 + threadIdx.x;
    if (i >= C2 * DMODEL * 5) return;
    int n   = i / (DMODEL * 5);
    int rem = i - n * (DMODEL * 5);
    int ch  = rem / 5;
    int tap = rem - ch * 5;
    wb[(size_t)n * 1280 + tap * DMODEL + ch] = w[i];
}

// ---------------- wmma tf32 conv(k=5) + GLU + residual ----------------
// One CTA: 128 time-rows x 64 GLU pairs (a-col n and g-col n+256), K=1280 streamed.
#define CPAD 40
#define EPAD 68
__global__ void __launch_bounds__(256) k_conv_wmma(
    const float* __restrict__ Xin, const float* __restrict__ Wb,
    const float* __restrict__ bias, float* __restrict__ out)
{
    __shared__ __align__(16) float sm[10240];   // 40 KB
    float* As = sm;              // [128][CPAD] row-major (m,k)
    float* Ba = sm + 5120;       // [64][CPAD]  col-major (k,n): elem(k,n) at n*CPAD+k
    float* Bg = sm + 7680;

    const int tid = threadIdx.x;
    const int wid = tid >> 5;
    const int m0 = blockIdx.x * 128;
    const int n0 = blockIdx.y * 64;
    const int wm = wid & 3;      // 4 m-tiles of 32 rows
    const int wn = wid >> 2;     // 2 n-tiles of 32 cols

    wmma::fragment<wmma::accumulator, 16, 16, 8, float> Ca[2][2], Cg[2][2];
    #pragma unroll
    for (int i = 0; i < 2; ++i)
        #pragma unroll
        for (int j = 0; j < 2; ++j) {
            wmma::fill_fragment(Ca[i][j], 0.0f);
            wmma::fill_fragment(Cg[i][j], 0.0f);
        }

    for (int c = 0; c < 40; ++c) {
        const int tap = c >> 3;
        const int ch0 = (c & 7) << 5;
        // A: 128 rows x 32 ch, causally shifted by (tap-4)
        #pragma unroll
        for (int i = 0; i < 4; ++i) {
            int e = tid + i * 256;
            int r = e >> 3, q = e & 7;
            int t = (m0 + r) & (TDEC - 1);
            float4 v = make_float4(0.f, 0.f, 0.f, 0.f);
            if (t + tap - 4 >= 0)
                v = *(const float4*)(Xin + (size_t)(m0 + r + tap - 4) * DMODEL + ch0 + q * 4);
            *(float4*)(As + r * CPAD + q * 4) = v;
        }
        // B: 64 a-rows + 64 g-rows x 32 k
        #pragma unroll
        for (int i = 0; i < 2; ++i) {
            int e = tid + i * 256;
            int n = e >> 3, q = e & 7;
            size_t ko = (size_t)(tap * DMODEL + ch0 + q * 4);
            *(float4*)(Ba + n * CPAD + q * 4) =
                *(const float4*)(Wb + (size_t)(n0 + n) * 1280 + ko);
            *(float4*)(Bg + n * CPAD + q * 4) =
                *(const float4*)(Wb + (size_t)(n0 + 256 + n) * 1280 + ko);
        }
        __syncthreads();
        #pragma unroll
        for (int ks = 0; ks < 4; ++ks) {
            wmma::fragment<wmma::matrix_a, 16, 16, 8, wmma::precision::tf32,
                           wmma::row_major> af[2];
            wmma::fragment<wmma::matrix_b, 16, 16, 8, wmma::precision::tf32,
                           wmma::col_major> bfa[2], bfg[2];
            #pragma unroll
            for (int mi = 0; mi < 2; ++mi) {
                wmma::load_matrix_sync(af[mi], As + (wm * 32 + mi * 16) * CPAD + ks * 8, CPAD);
                #pragma unroll
                for (int e = 0; e < af[mi].num_elements; ++e)
                    af[mi].x[e] = wmma::__float_to_tf32(af[mi].x[e]);
            }
            #pragma unroll
            for (int ni = 0; ni < 2; ++ni) {
                wmma::load_matrix_sync(bfa[ni], Ba + (wn * 32 + ni * 16) * CPAD + ks * 8, CPAD);
                wmma::load_matrix_sync(bfg[ni], Bg + (wn * 32 + ni * 16) * CPAD + ks * 8, CPAD);
                #pragma unroll
                for (int e = 0; e < bfa[ni].num_elements; ++e) {
                    bfa[ni].x[e] = wmma::__float_to_tf32(bfa[ni].x[e]);
                    bfg[ni].x[e] = wmma::__float_to_tf32(bfg[ni].x[e]);
                }
            }
            #pragma unroll
            for (int mi = 0; mi < 2; ++mi)
                #pragma unroll
                for (int ni = 0; ni < 2; ++ni) {
                    wmma::mma_sync(Ca[mi][ni], af[mi], bfa[ni], Ca[mi][ni]);
                    wmma::mma_sync(Cg[mi][ni], af[mi], bfg[ni], Cg[mi][ni]);
                }
        }
        __syncthreads();
    }

    // ---- epilogue: a accums -> smem -> regs; g accums -> smem; fuse GLU+residual ----
    float* Cb = sm;   // [128][EPAD], 34816 B, fits in the 40 KB block
    #pragma unroll
    for (int mi = 0; mi < 2; ++mi)
        #pragma unroll
        for (int ni = 0; ni < 2; ++ni)
            wmma::store_matrix_sync(Cb + (wm * 32 + mi * 16) * EPAD + wn * 32 + ni * 16,
                                    Ca[mi][ni], EPAD, wmma::mem_row_major);
    __syncthreads();
    const int r = tid >> 1;
    const int cc = (tid & 1) * 32;
    float av[32];
    #pragma unroll
    for (int q = 0; q < 8; ++q)
        *(float4*)&av[q * 4] = *(const float4*)(Cb + r * EPAD + cc + q * 4);
    __syncthreads();
    #pragma unroll
    for (int mi = 0; mi < 2; ++mi)
        #pragma unroll
        for (int ni = 0; ni < 2; ++ni)
            wmma::store_matrix_sync(Cb + (wm * 32 + mi * 16) * EPAD + wn * 32 + ni * 16,
                                    Cg[mi][ni], EPAD, wmma::mem_row_major);
    __syncthreads();
    {
        const int m = m0 + r;
        const float* xr = Xin + (size_t)m * DMODEL + n0 + cc;
        float* orow = out + (size_t)m * DMODEL + n0 + cc;
        #pragma unroll
        for (int q = 0; q < 8; ++q) {
            float4 g = *(const float4*)(Cb + r * EPAD + cc + q * 4);
            float4 res = *(const float4*)(xr + q * 4);
            float4 ba = *(const float4*)(bias + n0 + cc + q * 4);
            float4 bg = *(const float4*)(bias + 256 + n0 + cc + q * 4);
            float4 o;
            o.x = fmaf(av[q*4+0] + ba.x, sigf(g.x + bg.x), res.x) * RSQRT2;
            o.y = fmaf(av[q*4+1] + ba.y, sigf(g.y + bg.y), res.y) * RSQRT2;
            o.z = fmaf(av[q*4+2] + ba.z, sigf(g.z + bg.z), res.z) * RSQRT2;
            o.w = fmaf(av[q*4+3] + ba.w, sigf(g.w + bg.w), res.w) * RSQRT2;
            *(float4*)(orow + q * 4) = o;
        }
    }
}

// ---------------- K1: x = shift_right(mel @ W_lin^T + b_lin) ----------------
__global__ void __launch_bounds__(256) k_lin_shift(
    const float* __restrict__ mel, const float* __restrict__ W,
    const float* __restrict__ bias, float* __restrict__ out)
{
    __shared__ float As[16][128];
    __shared__ float Bs[16][64];
    const int tid = threadIdx.x;
    const int m0 = blockIdx.x * 128;
    const int n0 = blockIdx.y * 64;
    const int tx = tid & 15, ty = tid >> 4;
    u64 acc[4][4];
    #pragma unroll
    for (int i = 0; i < 4; ++i)
        #pragma unroll
        for (int j = 0; j < 4; ++j) acc[i][j] = 0ULL;

    for (int k0 = 0; k0 < INDIM; k0 += 16) {
        #pragma unroll
        for (int i = 0; i < 2; ++i) {
            int s = tid + i * 256;
            int r = s >> 2, kq = (s & 3) << 2;
            int m = m0 + r;
            int t = m & (TDEC - 1);
            float4 v = make_float4(0.f, 0.f, 0.f, 0.f);
            if (t > 0) v = *(const float4*)(mel + (size_t)(m - 1) * INDIM + k0 + kq);
            As[kq + 0][r] = v.x; As[kq + 1][r] = v.y; As[kq + 2][r] = v.z; As[kq + 3][r] = v.w;
        }
        {
            int n = tid >> 2, kq = (tid & 3) << 2;
            float4 v = *(const float4*)(W + (size_t)(n0 + n) * INDIM + k0 + kq);
            Bs[kq + 0][n] = v.x; Bs[kq + 1][n] = v.y; Bs[kq + 2][n] = v.z; Bs[kq + 3][n] = v.w;
        }
        __syncthreads();
        #pragma unroll
        for (int k = 0; k < 16; ++k) {
            ulonglong2 aa0 = *(const ulonglong2*)&As[k][ty * 8];
            ulonglong2 aa1 = *(const ulonglong2*)&As[k][ty * 8 + 4];
            float4 br = *(const float4*)&Bs[k][tx * 4];
            u64 b0 = pack_dup(br.x), b1 = pack_dup(br.y), b2 = pack_dup(br.z), b3 = pack_dup(br.w);
            ffma2(acc[0][0], aa0.x, b0); ffma2(acc[0][1], aa0.x, b1);
            ffma2(acc[0][2], aa0.x, b2); ffma2(acc[0][3], aa0.x, b3);
            ffma2(acc[1][0], aa0.y, b0); ffma2(acc[1][1], aa0.y, b1);
            ffma2(acc[1][2], aa0.y, b2); ffma2(acc[1][3], aa0.y, b3);
            ffma2(acc[2][0], aa1.x, b0); ffma2(acc[2][1], aa1.x, b1);
            ffma2(acc[2][2], aa1.x, b2); ffma2(acc[2][3], aa1.x, b3);
            ffma2(acc[3][0], aa1.y, b0); ffma2(acc[3][1], aa1.y, b1);
            ffma2(acc[3][2], aa1.y, b2); ffma2(acc[3][3], aa1.y, b3);
        }
        __syncthreads();
    }
    float4 bb = *(const float4*)(bias + n0 + tx * 4);
    #pragma unroll
    for (int i2 = 0; i2 < 4; ++i2) {
        float2 c0 = unpk(acc[i2][0]), c1 = unpk(acc[i2][1]);
        float2 c2 = unpk(acc[i2][2]), c3 = unpk(acc[i2][3]);
        int m = m0 + ty * 8 + 2 * i2;
        #pragma unroll
        for (int h = 0; h < 2; ++h) {
            int mm = m + h;
            int t = mm & (TDEC - 1);
            float4 o;
            if (t == 0) o = make_float4(0.f, 0.f, 0.f, 0.f);
            else if (h == 0)
                o = make_float4(c0.x + bb.x, c1.x + bb.y, c2.x + bb.z, c3.x + bb.w);
            else
                o = make_float4(c0.y + bb.x, c1.y + bb.y, c2.y + bb.z, c3.y + bb.w);
            *(float4*)(out + (size_t)mm * DMODEL + n0 + tx * 4) = o;
        }
    }
}

// ---------------- generic NK GEMM (FFMA2) ----------------
__global__ void __launch_bounds__(256) k_gemm_nk(
    const float* __restrict__ A, const float* __restrict__ Bw,
    const float* __restrict__ bias, float* __restrict__ out,
    int K, int ldc, size_t sA, size_t sB, size_t sO)
{
    A  += (size_t)blockIdx.z * sA;
    Bw += (size_t)blockIdx.z * sB;
    out += (size_t)blockIdx.z * sO;
    __shared__ float As[16][128];
    __shared__ float Bs[16][64];
    const int tid = threadIdx.x;
    const int m0 = blockIdx.x * 128;
    const int n0 = blockIdx.y * 64;
    const int tx = tid & 15, ty = tid >> 4;
    u64 acc[4][4];
    #pragma unroll
    for (int i = 0; i < 4; ++i)
        #pragma unroll
        for (int j = 0; j < 4; ++j) acc[i][j] = 0ULL;

    for (int k0 = 0; k0 < K; k0 += 16) {
        #pragma unroll
        for (int i = 0; i < 2; ++i) {
            int s = tid + i * 256;
            int r = s >> 2, kq = (s & 3) << 2;
            float4 v = *(const float4*)(A + (size_t)(m0 + r) * K + k0 + kq);
            As[kq + 0][r] = v.x; As[kq + 1][r] = v.y; As[kq + 2][r] = v.z; As[kq + 3][r] = v.w;
        }
        {
            int n = tid >> 2, kq = (tid & 3) << 2;
            float4 v = *(const float4*)(Bw + (size_t)(n0 + n) * K + k0 + kq);
            Bs[kq + 0][n] = v.x; Bs[kq + 1][n] = v.y; Bs[kq + 2][n] = v.z; Bs[kq + 3][n] = v.w;
        }
        __syncthreads();
        #pragma unroll
        for (int k = 0; k < 16; ++k) {
            ulonglong2 aa0 = *(const ulonglong2*)&As[k][ty * 8];
            ulonglong2 aa1 = *(const ulonglong2*)&As[k][ty * 8 + 4];
            float4 br = *(const float4*)&Bs[k][tx * 4];
            u64 b0 = pack_dup(br.x), b1 = pack_dup(br.y), b2 = pack_dup(br.z), b3 = pack_dup(br.w);
            ffma2(acc[0][0], aa0.x, b0); ffma2(acc[0][1], aa0.x, b1);
            ffma2(acc[0][2], aa0.x, b2); ffma2(acc[0][3], aa0.x, b3);
            ffma2(acc[1][0], aa0.y, b0); ffma2(acc[1][1], aa0.y, b1);
            ffma2(acc[1][2], aa0.y, b2); ffma2(acc[1][3], aa0.y, b3);
            ffma2(acc[2][0], aa1.x, b0); ffma2(acc[2][1], aa1.x, b1);
            ffma2(acc[2][2], aa1.x, b2); ffma2(acc[2][3], aa1.x, b3);
            ffma2(acc[3][0], aa1.y, b0); ffma2(acc[3][1], aa1.y, b1);
            ffma2(acc[3][2], aa1.y, b2); ffma2(acc[3][3], aa1.y, b3);
        }
        __syncthreads();
    }
    float4 bb = make_float4(0.f, 0.f, 0.f, 0.f);
    if (bias) bb = *(const float4*)(bias + n0 + tx * 4);
    #pragma unroll
    for (int i2 = 0; i2 < 4; ++i2) {
        float2 c0 = unpk(acc[i2][0]), c1 = unpk(acc[i2][1]);
        float2 c2 = unpk(acc[i2][2]), c3 = unpk(acc[i2][3]);
        int m = m0 + ty * 8 + 2 * i2;
        *(float4*)(out + (size_t)m * ldc + n0 + tx * 4) =
            make_float4(c0.x + bb.x, c1.x + bb.y, c2.x + bb.z, c3.x + bb.w);
        *(float4*)(out + (size_t)(m + 1) * ldc + n0 + tx * 4) =
            make_float4(c0.y + bb.x, c1.y + bb.y, c2.y + bb.z, c3.y + bb.w);
    }
}

// ---------------- one-pass softmax over rows of S ----------------
__global__ void __launch_bounds__(256) k_softmax(float* __restrict__ S)
{
    const size_t base = (size_t)blockIdx.x * TENC;
    const int tid = threadIdx.x;
    __shared__ float red[8];
    float4 v = *(const float4*)(S + base + tid * 4);
    float mx = fmaxf(fmaxf(v.x, v.y), fmaxf(v.z, v.w));
    #pragma unroll
    for (int o = 16; o > 0; o >>= 1) mx = fmaxf(mx, __shfl_xor_sync(0xffffffffu, mx, o));
    if ((tid & 31) == 0) red[tid >> 5] = mx;
    __syncthreads();
    mx = fmaxf(fmaxf(fmaxf(red[0], red[1]), fmaxf(red[2], red[3])),
               fmaxf(fmaxf(red[4], red[5]), fmaxf(red[6], red[7])));
    __syncthreads();
    v.x = __expf(v.x - mx); v.y = __expf(v.y - mx);
    v.z = __expf(v.z - mx); v.w = __expf(v.w - mx);
    float sm = v.x + v.y + v.z + v.w;
    #pragma unroll
    for (int o = 16; o > 0; o >>= 1) sm += __shfl_xor_sync(0xffffffffu, sm, o);
    if ((tid & 31) == 0) red[tid >> 5] = sm;
    __syncthreads();
    sm = red[0] + red[1] + red[2] + red[3] + red[4] + red[5] + red[6] + red[7];
    float inv = 1.0f / sm;
    v.x *= inv; v.y *= inv; v.z *= inv; v.w *= inv;
    *(float4*)(S + base + tid * 4) = v;
}

// ---------------- context: H1 = H0 + attn @ (enc + first), per batch ----------------
__global__ void __launch_bounds__(256) k_context(
    const float* __restrict__ S, const float* __restrict__ enc,
    const float* __restrict__ first, const float* __restrict__ H0,
    float* __restrict__ H1)
{
    const int b = blockIdx.z;
    const float* A = S + (size_t)b * TDEC * TENC;
    const float* E = enc + (size_t)b * TENC * DMODEL;
    const float* F = first + (size_t)b * TENC * DMODEL;
    __shared__ float As[16][128];
    __shared__ float Bs[16][64];
    const int tid = threadIdx.x;
    const int m0 = blockIdx.x * 128;
    const int n0 = blockIdx.y * 64;
    const int tx = tid & 15, ty = tid >> 4;
    u64 acc[4][4];
    #pragma unroll
    for (int i = 0; i < 4; ++i)
        #pragma unroll
        for (int j = 0; j < 4; ++j) acc[i][j] = 0ULL;

    for (int k0 = 0; k0 < TENC; k0 += 16) {
        #pragma unroll
        for (int i = 0; i < 2; ++i) {
            int s = tid + i * 256;
            int r = s >> 2, kq = (s & 3) << 2;
            float4 v = *(const float4*)(A + (size_t)(m0 + r) * TENC + k0 + kq);
            As[kq + 0][r] = v.x; As[kq + 1][r] = v.y; As[kq + 2][r] = v.z; As[kq + 3][r] = v.w;
        }
        {
            int kk = tid >> 4, nq = (tid & 15) << 2;
            float4 ve = *(const float4*)(E + (size_t)(k0 + kk) * DMODEL + n0 + nq);
            float4 vf = *(const float4*)(F + (size_t)(k0 + kk) * DMODEL + n0 + nq);
            *(float4*)&Bs[kk][nq] = make_float4(ve.x + vf.x, ve.y + vf.y,
                                                ve.z + vf.z, ve.w + vf.w);
        }
        __syncthreads();
        #pragma unroll
        for (int k = 0; k < 16; ++k) {
            ulonglong2 aa0 = *(const ulonglong2*)&As[k][ty * 8];
            ulonglong2 aa1 = *(const ulonglong2*)&As[k][ty * 8 + 4];
            float4 br = *(const float4*)&Bs[k][tx * 4];
            u64 b0 = pack_dup(br.x), b1 = pack_dup(br.y), b2 = pack_dup(br.z), b3 = pack_dup(br.w);
            ffma2(acc[0][0], aa0.x, b0); ffma2(acc[0][1], aa0.x, b1);
            ffma2(acc[0][2], aa0.x, b2); ffma2(acc[0][3], aa0.x, b3);
            ffma2(acc[1][0], aa0.y, b0); ffma2(acc[1][1], aa0.y, b1);
            ffma2(acc[1][2], aa0.y, b2); ffma2(acc[1][3], aa0.y, b3);
            ffma2(acc[2][0], aa1.x, b0); ffma2(acc[2][1], aa1.x, b1);
            ffma2(acc[2][2], aa1.x, b2); ffma2(acc[2][3], aa1.x, b3);
            ffma2(acc[3][0], aa1.y, b0); ffma2(acc[3][1], aa1.y, b1);
            ffma2(acc[3][2], aa1.y, b2); ffma2(acc[3][3], aa1.y, b3);
        }
        __syncthreads();
    }
    #pragma unroll
    for (int i2 = 0; i2 < 4; ++i2) {
        float2 c0 = unpk(acc[i2][0]), c1 = unpk(acc[i2][1]);
        float2 c2 = unpk(acc[i2][2]), c3 = unpk(acc[i2][3]);
        size_t m = (size_t)b * TDEC + m0 + ty * 8 + 2 * i2;
        float4 h0 = *(const float4*)(H0 + m * DMODEL + n0 + tx * 4);
        *(float4*)(H1 + m * DMODEL + n0 + tx * 4) =
            make_float4(c0.x + h0.x, c1.x + h0.y, c2.x + h0.z, c3.x + h0.w);
        float4 h1 = *(const float4*)(H0 + (m + 1) * DMODEL + n0 + tx * 4);
        *(float4*)(H1 + (m + 1) * DMODEL + n0 + tx * 4) =
            make_float4(c0.y + h1.x, c1.y + h1.y, c2.y + h1.z, c3.y + h1.w);
    }
}

// ---------------- final projection (N=80, predicated) ----------------
__global__ void __launch_bounds__(256) k_proj(
    const float* __restrict__ A, const float* __restrict__ W,
    const float* __restrict__ bias, float* __restrict__ out)
{
    __shared__ float As[16][128];
    __shared__ float Bs[16][64];
    const int tid = threadIdx.x;
    const int m0 = blockIdx.x * 128;
    const int n0 = blockIdx.y * 64;
    const int tx = tid & 15, ty = tid >> 4;
    u64 acc[4][4];
    #pragma unroll
    for (int i = 0; i < 4; ++i)
        #pragma unroll
        for (int j = 0; j < 4; ++j) acc[i][j] = 0ULL;

    for (int k0 = 0; k0 < DMODEL; k0 += 16) {
        #pragma unroll
        for (int i = 0; i < 2; ++i) {
            int s = tid + i * 256;
            int r = s >> 2, kq = (s & 3) << 2;
            float4 v = *(const float4*)(A + (size_t)(m0 + r) * DMODEL + k0 + kq);
            As[kq + 0][r] = v.x; As[kq + 1][r] = v.y; As[kq + 2][r] = v.z; As[kq + 3][r] = v.w;
        }
        {
            int n = tid >> 2, kq = (tid & 3) << 2;
            float4 v = make_float4(0.f, 0.f, 0.f, 0.f);
            if (n0 + n < INDIM)
                v = *(const float4*)(W + (size_t)(n0 + n) * DMODEL + k0 + kq);
            Bs[kq + 0][n] = v.x; Bs[kq + 1][n] = v.y; Bs[kq + 2][n] = v.z; Bs[kq + 3][n] = v.w;
        }
        __syncthreads();
        #pragma unroll
        for (int k = 0; k < 16; ++k) {
            ulonglong2 aa0 = *(const ulonglong2*)&As[k][ty * 8];
            ulonglong2 aa1 = *(const ulonglong2*)&As[k][ty * 8 + 4];
            float4 br = *(const float4*)&Bs[k][tx * 4];
            u64 b0 = pack_dup(br.x), b1 = pack_dup(br.y), b2 = pack_dup(br.z), b3 = pack_dup(br.w);
            ffma2(acc[0][0], aa0.x, b0); ffma2(acc[0][1], aa0.x, b1);
            ffma2(acc[0][2], aa0.x, b2); ffma2(acc[0][3], aa0.x, b3);
            ffma2(acc[1][0], aa0.y, b0); ffma2(acc[1][1], aa0.y, b1);
            ffma2(acc[1][2], aa0.y, b2); ffma2(acc[1][3], aa0.y, b3);
            ffma2(acc[2][0], aa1.x, b0); ffma2(acc[2][1], aa1.x, b1);
            ffma2(acc[2][2], aa1.x, b2); ffma2(acc[2][3], aa1.x, b3);
            ffma2(acc[3][0], aa1.y, b0); ffma2(acc[3][1], aa1.y, b1);
            ffma2(acc[3][2], aa1.y, b2); ffma2(acc[3][3], aa1.y, b3);
        }
        __syncthreads();
    }
    int col = n0 + tx * 4;
    if (col < INDIM) {
        float4 bb = *(const float4*)(bias + col);
        #pragma unroll
        for (int i2 = 0; i2 < 4; ++i2) {
            float2 c0 = unpk(acc[i2][0]), c1 = unpk(acc[i2][1]);
            float2 c2 = unpk(acc[i2][2]), c3 = unpk(acc[i2][3]);
            int m = m0 + ty * 8 + 2 * i2;
            *(float4*)(out + (size_t)m * INDIM + col) =
                make_float4(c0.x + bb.x, c1.x + bb.y, c2.x + bb.z, c3.x + bb.w);
            *(float4*)(out + (size_t)(m + 1) * INDIM + col) =
                make_float4(c0.y + bb.x, c1.y + bb.y, c2.y + bb.z, c3.y + bb.w);
        }
    }
}

// ---------------- launch ----------------
extern "C" void kernel_launch(void* const* d_in, const int* in_sizes, int n_in,
                              void* d_out, int out_size)
{
    (void)in_sizes; (void)n_in; (void)out_size;
    const float* enc   = (const float*)d_in[0];
    const float* first = (const float*)d_in[1];
    const float* mel   = (const float*)d_in[2];
    const float* W_lin = (const float*)d_in[3];
    const float* b_lin = (const float*)d_in[4];
    const float* cw0   = (const float*)d_in[5];
    const float* cb0   = (const float*)d_in[6];
    const float* cw1   = (const float*)d_in[7];
    const float* cb1   = (const float*)d_in[8];
    const float* W_att = (const float*)d_in[9];
    const float* b_att = (const float*)d_in[10];
    const float* W_prj = (const float*)d_in[11];
    const float* b_prj = (const float*)d_in[12];
    float* out = (float*)d_out;

    float *X, *H0, *Q, *H1, *S, *Wb0, *Wb1;
    cudaGetSymbolAddress((void**)&X,  g_X);
    cudaGetSymbolAddress((void**)&H0, g_H0);
    cudaGetSymbolAddress((void**)&Q,  g_Q);
    cudaGetSymbolAddress((void**)&H1, g_H1);
    cudaGetSymbolAddress((void**)&S,  g_S);
    cudaGetSymbolAddress((void**)&Wb0, g_Wb0);
    cudaGetSymbolAddress((void**)&Wb1, g_Wb1);

    k_repack_nk<<<(C2 * DMODEL * 5 + 255) / 256, 256>>>(cw0, Wb0);
    k_repack_nk<<<(C2 * DMODEL * 5 + 255) / 256, 256>>>(cw1, Wb1);
    k_lin_shift<<<dim3(MTOT / 128, DMODEL / 64), 256>>>(mel, W_lin, b_lin, X);
    k_conv_wmma<<<dim3(MTOT / 128, DMODEL / 64), 256>>>(X, Wb0, cb0, H0);
    k_gemm_nk<<<dim3(MTOT / 128, DMODEL / 64, 1), 256>>>(
        H0, W_att, b_att, Q, DMODEL, DMODEL, 0, 0, 0);
    k_gemm_nk<<<dim3(TDEC / 128, TENC / 64, BDIM), 256>>>(
        Q, enc, nullptr, S, DMODEL, TENC,
        (size_t)TDEC * DMODEL, (size_t)TENC * DMODEL, (size_t)TDEC * TENC);
    k_softmax<<<MTOT, 256>>>(S);
    k_context<<<dim3(TDEC / 128, DMODEL / 64, BDIM), 256>>>(S, enc, first, H0, H1);
    k_conv_wmma<<<dim3(MTOT / 128, DMODEL / 64), 256>>>(H1, Wb1, cb1, X);
    k_proj<<<dim3(MTOT / 128, 2), 256>>>(X, W_prj, b_prj, out);
}